// round 9
// baseline (speedup 1.0000x reference)
#include <cuda_runtime.h>
#include <cstdint>

// Problem constants (match reference)
#define BN 64
#define TN 1024
#define DN 256
#define KMAX 128
#define EPSF 1e-3f
#define MMAXT 64                        // lgamma table depth
#define HALF_L2PI 0.91893853320467274f  // 0.5*log(2*pi)
#define LN2F 0.69314718055994531f
#define LOG2EF 1.44269504088896340f
// C1 = ln(log2e) - 0.5*ln(pi)  (per-nonzero-obs constant from log2 scaling)
#define C1F (-0.20585202294f)

// ---------------------------------------------------------------------------
// Static device scratch
// ---------------------------------------------------------------------------
__device__ int   g_cnt [BN * KMAX];
__device__ int   g_list[BN * KMAX * TN];   // PRE-SCALED float4-row offsets: t * (DN/4)

// per-dim packed loop constants: {kappa0, a, kl2, cb}
__device__ float4 g_c4[DN];
// fallback-path constants
__device__ float g_a0[DN], g_b0[DN];
__device__ float g_lgA0B0[DN], g_lgA0[DN], g_lgB0[DN], g_lgA[DN], g_lgK[DN];

// lgamma difference tables (telescoped chain-end sums)
__device__ float g_tabNZ[MMAXT * DN];   // [lg(a0+m)-lg(a0)] + [lg(a+m/2)-lg(a)] + [lg(k0+m)-lg(k0)]
__device__ float g_tabB0[MMAXT * DN];   // lg(b0+m)-lg(b0)
__device__ float g_tabAB[MMAXT * DN];   // lg(a0+b0+m)-lg(a0+b0)

// ---------------------------------------------------------------------------
// Fast lgamma for x > 0: shift to x>=8 (unrolled, predicated), then Stirling.
// ---------------------------------------------------------------------------
__device__ __forceinline__ float fast_lgamma(float x)
{
    float prod = 1.0f;
#pragma unroll
    for (int i = 0; i < 8; i++) {
        if (x < 8.0f) { prod *= x; x += 1.0f; }
    }
    float rx  = __frcp_rn(x);
    float rx2 = rx * rx;
    float ser = rx * (8.33333333e-2f + rx2 * (-2.77777778e-3f + rx2 * 7.93650794e-4f));
    float lx  = __logf(x);
    return fmaf(x - 0.5f, lx, -x) + HALF_L2PI + ser - __logf(prod);
}

// ---------------------------------------------------------------------------
// Kernel 1 (fused prep): blocks [0, MMAXT) build lgamma tables + constants;
// blocks [MMAXT, MMAXT+8) build per-(b,k) time lists (one warp per batch row).
// ---------------------------------------------------------------------------
__global__ void __launch_bounds__(256)
k_prep(const float* __restrict__ loc,
       const float* __restrict__ log_mean_conc,
       const float* __restrict__ log_conc,
       const float* __restrict__ log_scale,
       const float* __restrict__ sparse_prior_logit,
       const int*   __restrict__ z,
       float* __restrict__ out)
{
    if (blockIdx.x < MMAXT) {
        const int m = blockIdx.x;
        const int d = threadIdx.x;
        float kappa0 = expf(fminf(log_mean_conc[d], 12.0f));
        float a      = expf(log_conc[d]);
        float b      = expf(log_scale[d]);
        float a0     = 2.0f * a + 4.0f;                 // nu+1, nu = 2a+3
        float b0     = a0 * expf(sparse_prior_logit[d]);
        float l      = loc[d];

        float lgA0 = fast_lgamma(a0);
        float lgB0 = fast_lgamma(b0);
        float lgAB = fast_lgamma(a0 + b0);
        float lgA  = fast_lgamma(a);
        float lgK  = fast_lgamma(kappa0);

        if (m == 0) {
            g_c4[d] = make_float4(kappa0, a,
                                  LOG2EF * kappa0 * l,
                                  (LOG2EF * LOG2EF) * fmaf(kappa0 * l, l, 2.0f * b));
            g_a0[d]     = a0;
            g_b0[d]     = b0;
            // exact bases for the (rare) cnt>=MMAXT fallback path
            g_lgA0[d]   = lgammaf(a0);
            g_lgB0[d]   = lgammaf(b0);
            g_lgA0B0[d] = lgammaf(a0 + b0);
            g_lgA[d]    = lgammaf(a);
            g_lgK[d]    = lgammaf(kappa0);
            if (d < BN) out[d] = 0.0f;                  // out is poisoned
        }

        float fm = (float)m;
        g_tabNZ[m * DN + d] = (fast_lgamma(a0 + fm)           - lgA0)
                            + (fast_lgamma(fmaf(0.5f, fm, a)) - lgA)
                            + (fast_lgamma(kappa0 + fm)       - lgK);
        g_tabB0[m * DN + d] = fast_lgamma(b0 + fm)            - lgB0;
        g_tabAB[m * DN + d] = fast_lgamma(a0 + b0 + fm)       - lgAB;
    } else {
        // ---- list build: one warp per batch row ----
        __shared__ int cs[8][KMAX];
        const int wl   = threadIdx.x >> 5;
        const int lane = threadIdx.x & 31;
        const int b    = (blockIdx.x - MMAXT) * 8 + wl;

        for (int i = threadIdx.x; i < 8 * KMAX; i += blockDim.x)
            ((int*)cs)[i] = 0;
        __syncthreads();

        const int* zr = z + b * TN;
        int* cw = cs[wl];
        const unsigned lmlt = (1u << lane) - 1u;

        for (int t0 = 0; t0 < TN; t0 += 32) {
            int t  = t0 + lane;
            int zv = __ldg(zr + t);                          // coalesced
            unsigned mask = __match_any_sync(0xffffffffu, zv);
            int rank = __popc(mask & lmlt);                  // stable in-chunk rank
            int base = cw[zv];
            __syncwarp();
            // store PRE-SCALED float4-row offset: t * (DN/4)
            g_list[((size_t)(b * KMAX + zv)) * TN + base + rank] = t * (DN / 4);
            if (rank == 0)
                cw[zv] = base + __popc(mask);
            __syncwarp();
        }

        for (int k = lane; k < KMAX; k += 32)
            g_cnt[b * KMAX + k] = cw[k];
    }
}

// ---------------------------------------------------------------------------
// Per-observation update, branchless + division-free (log2 domain).
// State: w = kl2 + Sum(nz*y), s2p = cb + Sum(nz*y^2), kn = kappa0 + m1,
//        an = a + m1/2.  With e = y*kn - w, P = (s2p*kn - w^2)(kn+1),
//        Q = P + e^2:  obs term = an*log2(P) - (an+0.5)*log2(Q)
// (the +log2(kn) residue telescopes into tabNZ; scale residue is C1 per obs).
// A masked/padded observation (x = 0) is a no-op: nzf = 0 leaves all state
// and the accumulator unchanged.
// ---------------------------------------------------------------------------
__device__ __forceinline__ void obs2(float x,
                                     float& w, float& s2p, float& kn, float& an,
                                     float& acc2)
{
    float nzf = (x > EPSF) ? 1.0f : 0.0f;
    float y   = __log2f(fmaxf(x, EPSF));
    float e   = fmaf(y, kn, -w);
    float t1  = fmaf(s2p, kn, -w * w);
    float kn1 = kn + 1.0f;
    float P   = t1 * kn1;
    float Q   = fmaf(e, e, P);
    float LP  = __log2f(P);
    float LQ  = __log2f(Q);
    float th  = fmaf(an, LP - LQ, -0.5f * LQ);
    acc2 = fmaf(nzf, th, acc2);
    float yn = y * nzf;
    w   += yn;
    s2p  = fmaf(yn, y, s2p);
    kn  += nzf;
    an   = fmaf(0.5f, nzf, an);
}

// Chain-end telescoped terms for one dim (natural units; s1 in log2 units).
__device__ __forceinline__ float tail2(int d, int cnt, float m1, float s1,
                                       float a, float kap)
{
    const int M1 = (int)m1;
    const int Z  = cnt - M1;
    float r = fmaf(C1F, m1, -LN2F * s1);   // folded -0.5*ln(pi), scale fix, -Sum y
    if (cnt < MMAXT) {
        r += g_tabNZ[M1 * DN + d]      // nonzero-obs lgamma ratios (3 fused)
           + g_tabB0[Z  * DN + d]      // Sum log(b0+n0)          (zero obs)
           - g_tabAB[cnt * DN + d];    // -Sum log(a0+b0+ck)
    } else {
        float a0 = g_a0[d], b0 = g_b0[d];
        r += (lgammaf(a0 + m1)             - g_lgA0[d])
           + (lgammaf(b0 + (float)Z)       - g_lgB0[d])
           + (lgammaf(fmaf(0.5f, m1, a))   - g_lgA[d])
           + (lgammaf(kap + m1)            - g_lgK[d])
           - (lgammaf(a0 + b0 + (float)cnt) - g_lgA0B0[d]);
    }
    return r;
}

// ---------------------------------------------------------------------------
// Kernel 2: main chain evaluation.
// One CTA per (b,k) chain, 64 threads; thread t owns dims 4t..4t+3. The CTA
// streams its cluster's X rows as coalesced float4 (full 1KB row / iter),
// unrolled 2 time-steps per loop with depth-2 prefetch; odd trip counts are
// handled by masking the padded slot to x = 0 (no-op through obs2).
// ---------------------------------------------------------------------------
__global__ void __launch_bounds__(64)
k_main(const float* __restrict__ X, float* __restrict__ out)
{
    const int id = blockIdx.x;            // chain id = b*KMAX + k
    const int b  = id >> 7;
    const int k  = id & (KMAX - 1);
    const int t  = threadIdx.x;           // dims 4t..4t+3

    const int cnt = g_cnt[id];
    float accN = 0.0f;

    if (cnt > 0) {
        const float4 C0 = __ldg(&g_c4[4 * t]);
        const float4 C1 = __ldg(&g_c4[4 * t + 1]);
        const float4 C2 = __ldg(&g_c4[4 * t + 2]);
        const float4 C3 = __ldg(&g_c4[4 * t + 3]);

        const int* lst = g_list + (size_t)id * TN;
        const float4* Xb = (const float4*)X + ((size_t)b * TN) * (DN / 4) + t;

        float w0 = C0.z, p0 = C0.w, n0 = C0.x, a0_ = C0.y;
        float w1 = C1.z, p1 = C1.w, n1 = C1.x, a1_ = C1.y;
        float w2 = C2.z, p2 = C2.w, n2 = C2.x, a2_ = C2.y;
        float w3 = C3.z, p3 = C3.w, n3 = C3.x, a3_ = C3.y;
        float acc2 = 0.f;

        const int cl = cnt - 1;
        int oa = __ldg(lst);                       // pre-scaled row offsets
        int ob = __ldg(lst + min(1, cl));
        float4 x0 = __ldg(Xb + (size_t)oa);
        float4 x1 = __ldg(Xb + (size_t)ob);

        const int cnt2 = (cnt + 1) & ~1;           // round up to even
        for (int j = 0; j < cnt2; j += 2) {
            int on0 = __ldg(lst + min(j + 2, cl));
            int on1 = __ldg(lst + min(j + 3, cl));
            float4 xn0 = __ldg(Xb + (size_t)on0);
            float4 xn1 = __ldg(Xb + (size_t)on1);

            // slot 0 (always in range: j < cnt)
            obs2(x0.x, w0, p0, n0, a0_, acc2);
            obs2(x0.y, w1, p1, n1, a1_, acc2);
            obs2(x0.z, w2, p2, n2, a2_, acc2);
            obs2(x0.w, w3, p3, n3, a3_, acc2);

            // slot 1 (mask padded element to 0 -> no-op)
            float msk = (j + 1 < cnt) ? 1.0f : 0.0f;
            obs2(x1.x * msk, w0, p0, n0, a0_, acc2);
            obs2(x1.y * msk, w1, p1, n1, a1_, acc2);
            obs2(x1.z * msk, w2, p2, n2, a2_, acc2);
            obs2(x1.w * msk, w3, p3, n3, a3_, acc2);

            x0 = xn0;
            x1 = xn1;
        }

        const int d0 = 4 * t;
        accN  = tail2(d0,     cnt, rintf(n0 - C0.x), w0 - C0.z, C0.y, C0.x);
        accN += tail2(d0 + 1, cnt, rintf(n1 - C1.x), w1 - C1.z, C1.y, C1.x);
        accN += tail2(d0 + 2, cnt, rintf(n2 - C2.x), w2 - C2.z, C2.y, C2.x);
        accN += tail2(d0 + 3, cnt, rintf(n3 - C3.x), w3 - C3.z, C3.y, C3.x);
        accN  = fmaf(LN2F, acc2, accN);
    }

    // CRP (fully telescoped): Sum_k lgamma(cnt_k) - lgamma(T+1) per batch row
    if (t == 0) {
        if (cnt > 0) accN += fast_lgamma((float)cnt);
        if (k == 0)  accN -= lgammaf((float)(TN + 1));
    }

    // 2-warp reduction
    const int lane = t & 31, wid = t >> 5;
#pragma unroll
    for (int o = 16; o; o >>= 1)
        accN += __shfl_down_sync(0xffffffffu, accN, o);
    __shared__ float wsum[2];
    if (lane == 0) wsum[wid] = accN;
    __syncthreads();
    if (t == 0)
        atomicAdd(&out[b], -(wsum[0] + wsum[1]));
}

// ---------------------------------------------------------------------------
// Entry point. Inputs: X, loc, log_mean_conc, log_conc, log_scale,
// sparse_prior_logit, z. Output: float[BN].
// ---------------------------------------------------------------------------
extern "C" void kernel_launch(void* const* d_in, const int* in_sizes, int n_in,
                              void* d_out, int out_size)
{
    const float* X   = (const float*)d_in[0];
    const float* loc = (const float*)d_in[1];
    const float* lmc = (const float*)d_in[2];
    const float* lc  = (const float*)d_in[3];
    const float* ls  = (const float*)d_in[4];
    const float* spl = (const float*)d_in[5];
    const int*   z   = (const int*)d_in[6];
    float* out = (float*)d_out;

    k_prep<<<MMAXT + BN / 8, 256>>>(loc, lmc, lc, ls, spl, z, out);
    k_main<<<BN * KMAX, 64>>>(X, out);
}

// round 10
// speedup vs baseline: 1.3207x; 1.3207x over previous
#include <cuda_runtime.h>
#include <cstdint>

// Problem constants (match reference)
#define BN 64
#define TN 1024
#define DN 256
#define KMAX 128
#define EPSF 1e-3f
#define MMAXT 64                        // table depth (max cluster size covered)
#define HALF_L2PI 0.91893853320467274f  // 0.5*log(2*pi)
#define LN2F 0.69314718055994531f
#define LOG2EF 1.44269504088896340f
// C1 = ln(log2e) - 0.5*ln(pi)  (per-nonzero-obs scale residue)
#define C1F (-0.20585202294f)

// ---------------------------------------------------------------------------
// Static device scratch
// ---------------------------------------------------------------------------
__device__ int   g_cnt [BN * KMAX];
__device__ int   g_list[BN * KMAX * TN];   // PRE-SCALED float4-row offsets: t * (DN/4)

// per-dim packed loop constants: {kappa0, a, kl2, cb}
__device__ float4 g_c4[DN];
// fallback-path constants
__device__ float g_a0[DN], g_b0[DN];
__device__ float g_lgA0B0[DN], g_lgA0[DN], g_lgB0[DN], g_lgA[DN], g_lgK[DN];

// tables indexed by count m (telescoped chain-end sums)
// g_tabNZ[m][d] = [lg(a0+m)-lg(a0)] + [lg(a+m/2)-lg(a)] + [lg(k0+m)-lg(k0)]
//               + LN2 * [ a*log2(P0_sc) + Sum_{i=0}^{m-2}(a+(i+1)/2)*log2((k0+i+2)/(k0+i)) ]
__device__ float g_tabNZ[MMAXT * DN];
__device__ float g_tabB0[MMAXT * DN];   // lg(b0+m)-lg(b0)
__device__ float g_tabAB[MMAXT * DN];   // lg(a0+b0+m)-lg(a0+b0)

// ---------------------------------------------------------------------------
// Fast lgamma for x > 0: shift to x>=8 (unrolled, predicated), then Stirling.
// ---------------------------------------------------------------------------
__device__ __forceinline__ float fast_lgamma(float x)
{
    float prod = 1.0f;
#pragma unroll
    for (int i = 0; i < 8; i++) {
        if (x < 8.0f) { prod *= x; x += 1.0f; }
    }
    float rx  = __frcp_rn(x);
    float rx2 = rx * rx;
    float ser = rx * (8.33333333e-2f + rx2 * (-2.77777778e-3f + rx2 * 7.93650794e-4f));
    float lx  = __logf(x);
    return fmaf(x - 0.5f, lx, -x) + HALF_L2PI + ser - __logf(prod);
}

// ---------------------------------------------------------------------------
// Kernel 1 (fused prep): blocks [0, MMAXT) build tables + constants;
// blocks [MMAXT, MMAXT+8) build per-(b,k) time lists (one warp per batch row).
// ---------------------------------------------------------------------------
__global__ void __launch_bounds__(256)
k_prep(const float* __restrict__ loc,
       const float* __restrict__ log_mean_conc,
       const float* __restrict__ log_conc,
       const float* __restrict__ log_scale,
       const float* __restrict__ sparse_prior_logit,
       const int*   __restrict__ z,
       float* __restrict__ out)
{
    if (blockIdx.x < MMAXT) {
        const int m = blockIdx.x;
        const int d = threadIdx.x;
        float kappa0 = expf(fminf(log_mean_conc[d], 12.0f));
        float a      = expf(log_conc[d]);
        float b      = expf(log_scale[d]);
        float a0     = 2.0f * a + 4.0f;                 // nu+1, nu = 2a+3
        float b0     = a0 * expf(sparse_prior_logit[d]);
        float l      = loc[d];
        float kl2    = LOG2EF * kappa0 * l;
        float cb     = (LOG2EF * LOG2EF) * fmaf(kappa0 * l, l, 2.0f * b);

        float lgA0 = fast_lgamma(a0);
        float lgB0 = fast_lgamma(b0);
        float lgAB = fast_lgamma(a0 + b0);
        float lgA  = fast_lgamma(a);
        float lgK  = fast_lgamma(kappa0);

        if (m == 0) {
            g_c4[d] = make_float4(kappa0, a, kl2, cb);
            g_a0[d]     = a0;
            g_b0[d]     = b0;
            // exact bases for the (rare) cnt>=MMAXT fallback path
            g_lgA0[d]   = lgammaf(a0);
            g_lgB0[d]   = lgammaf(b0);
            g_lgA0B0[d] = lgammaf(a0 + b0);
            g_lgA[d]    = lgammaf(a);
            g_lgK[d]    = lgammaf(kappa0);
            if (d < BN) out[d] = 0.0f;                  // out is poisoned
        }

        float fm = (float)m;
        // telescoped Student-t constant part (log2 scaled units)
        float tc = 0.0f;
        if (m >= 1) {
            float t10 = fmaf(cb, kappa0, -kl2 * kl2);   // t1 at M=0 (scaled)
            float p0  = t10 * (kappa0 + 1.0f);
            tc = a * __log2f(p0);
            for (int i = 0; i + 2 <= m; i++) {
                float ratio = __fdividef(kappa0 + (float)(i + 2), kappa0 + (float)i);
                tc = fmaf(fmaf(0.5f, (float)(i + 1), a), __log2f(ratio), tc);
            }
        }
        g_tabNZ[m * DN + d] = (fast_lgamma(a0 + fm)           - lgA0)
                            + (fast_lgamma(fmaf(0.5f, fm, a)) - lgA)
                            + (fast_lgamma(kappa0 + fm)       - lgK)
                            + LN2F * tc;
        g_tabB0[m * DN + d] = fast_lgamma(b0 + fm)            - lgB0;
        g_tabAB[m * DN + d] = fast_lgamma(a0 + b0 + fm)       - lgAB;
    } else {
        // ---- list build: one warp per batch row ----
        __shared__ int cs[8][KMAX];
        const int wl   = threadIdx.x >> 5;
        const int lane = threadIdx.x & 31;
        const int b    = (blockIdx.x - MMAXT) * 8 + wl;

        for (int i = threadIdx.x; i < 8 * KMAX; i += blockDim.x)
            ((int*)cs)[i] = 0;
        __syncthreads();

        const int* zr = z + b * TN;
        int* cw = cs[wl];
        const unsigned lmlt = (1u << lane) - 1u;

        for (int t0 = 0; t0 < TN; t0 += 32) {
            int t  = t0 + lane;
            int zv = __ldg(zr + t);                          // coalesced
            unsigned mask = __match_any_sync(0xffffffffu, zv);
            int rank = __popc(mask & lmlt);                  // stable in-chunk rank
            int base = cw[zv];
            __syncwarp();
            g_list[((size_t)(b * KMAX + zv)) * TN + base + rank] = t * (DN / 4);
            if (rank == 0)
                cw[zv] = base + __popc(mask);
            __syncwarp();
        }

        for (int k = lane; k < KMAX; k += 32)
            g_cnt[b * KMAX + k] = cw[k];
    }
}

// ---------------------------------------------------------------------------
// Sufficient-stat-only per-element update (the whole Student-t log sum is
// telescoped out of the loop). A padded/zero element is a no-op.
// ---------------------------------------------------------------------------
__device__ __forceinline__ void obs_lite(float x, float& w, float& s2p, float& m1)
{
    float nzf = (x > EPSF) ? 1.0f : 0.0f;
    float y   = __log2f(fmaxf(x, EPSF));
    float yn  = y * nzf;
    w   += yn;
    s2p  = fmaf(yn, y, s2p);
    m1  += nzf;
}

// ---------------------------------------------------------------------------
// Chain-end terms for one dim. Telescoped Student-t final term:
//   - (a + M/2) * ln Q_final, Q_final = (s2p*kn - w^2) * (kn - 1), kn = k0 + M
// plus table-telescoped hurdle/CRP-emission lgamma sums.
// ---------------------------------------------------------------------------
__device__ __forceinline__ float tail3(int d, int cnt, float m1, float w, float s2p,
                                       float kap, float a, float kl2)
{
    const int M1 = (int)m1;
    const int Z  = cnt - M1;
    float s1  = w - kl2;
    float kn  = kap + m1;
    float t1f = fmaf(s2p, kn, -w * w);
    float qf  = t1f * (kn - 1.0f);
    float lq  = __log2f(fmaxf(qf, 1e-37f));
    float cf  = (m1 > 0.5f) ? fmaf(0.5f, m1, a) : 0.0f;   // gate M=0 (qf may be <=0)
    float r = fmaf(C1F, m1, -LN2F * s1);     // -0.5*ln(pi) residue, -Sum y
    r -= LN2F * cf * lq;                     // -(a+M/2)*ln(Q_final)
    if (cnt < MMAXT) {
        r += g_tabNZ[M1 * DN + d]      // nonzero-obs lgammas + telescoped t const
           + g_tabB0[Z  * DN + d]      // Sum log(b0+n0)       (zero obs)
           - g_tabAB[cnt * DN + d];    // -Sum log(a0+b0+ck)
    } else {
        // rare fallback: direct evaluation
        float a0 = g_a0[d], b0 = g_b0[d];
        float tc = 0.0f;
        if (M1 >= 1) {
            float cb_eq = s2p;  // not used; recompute P0 from stored constants
            (void)cb_eq;
            float t10 = fmaf(((const float4*)g_c4)[d].w, kap, -kl2 * kl2);
            float p0  = t10 * (kap + 1.0f);
            tc = a * __log2f(p0);
            for (int i = 0; i + 2 <= M1; i++) {
                float ratio = __fdividef(kap + (float)(i + 2), kap + (float)i);
                tc = fmaf(fmaf(0.5f, (float)(i + 1), a), __log2f(ratio), tc);
            }
        }
        r += LN2F * tc
           + (lgammaf(a0 + m1)              - g_lgA0[d])
           + (lgammaf(b0 + (float)Z)        - g_lgB0[d])
           + (lgammaf(fmaf(0.5f, m1, a))    - g_lgA[d])
           + (lgammaf(kap + m1)             - g_lgK[d])
           - (lgammaf(a0 + b0 + (float)cnt) - g_lgA0B0[d]);
    }
    return r;
}

// ---------------------------------------------------------------------------
// Kernel 2: main chain evaluation.
// One CTA per (b,k) chain, 64 threads; thread t owns dims 4t..4t+3. The CTA
// streams its cluster's X rows as coalesced float4, 2 time-steps per loop
// with depth-2 prefetch; odd trip counts are masked to x=0 (no-op).
// The loop only accumulates sufficient statistics (7 instr/element).
// ---------------------------------------------------------------------------
__global__ void __launch_bounds__(64)
k_main(const float* __restrict__ X, float* __restrict__ out)
{
    const int id = blockIdx.x;            // chain id = b*KMAX + k
    const int b  = id >> 7;
    const int k  = id & (KMAX - 1);
    const int t  = threadIdx.x;           // dims 4t..4t+3

    const int cnt = g_cnt[id];
    float accN = 0.0f;

    if (cnt > 0) {
        const float4 C0 = __ldg(&g_c4[4 * t]);      // {kappa0, a, kl2, cb}
        const float4 C1 = __ldg(&g_c4[4 * t + 1]);
        const float4 C2 = __ldg(&g_c4[4 * t + 2]);
        const float4 C3 = __ldg(&g_c4[4 * t + 3]);

        const int* lst = g_list + (size_t)id * TN;
        const float4* Xb = (const float4*)X + ((size_t)b * TN) * (DN / 4) + t;

        float w0 = C0.z, p0 = C0.w, m0 = 0.f;
        float w1 = C1.z, p1 = C1.w, m1 = 0.f;
        float w2 = C2.z, p2 = C2.w, m2 = 0.f;
        float w3 = C3.z, p3 = C3.w, m3 = 0.f;

        const int cl = cnt - 1;
        int oa = __ldg(lst);                       // pre-scaled row offsets
        int ob = __ldg(lst + min(1, cl));
        float4 x0 = __ldg(Xb + (size_t)oa);
        float4 x1 = __ldg(Xb + (size_t)ob);

        const int cnt2 = (cnt + 1) & ~1;           // round up to even
        for (int j = 0; j < cnt2; j += 2) {
            int on0 = __ldg(lst + min(j + 2, cl));
            int on1 = __ldg(lst + min(j + 3, cl));
            float4 xn0 = __ldg(Xb + (size_t)on0);
            float4 xn1 = __ldg(Xb + (size_t)on1);

            obs_lite(x0.x, w0, p0, m0);
            obs_lite(x0.y, w1, p1, m1);
            obs_lite(x0.z, w2, p2, m2);
            obs_lite(x0.w, w3, p3, m3);

            float msk = (j + 1 < cnt) ? 1.0f : 0.0f;
            obs_lite(x1.x * msk, w0, p0, m0);
            obs_lite(x1.y * msk, w1, p1, m1);
            obs_lite(x1.z * msk, w2, p2, m2);
            obs_lite(x1.w * msk, w3, p3, m3);

            x0 = xn0;
            x1 = xn1;
        }

        const int d0 = 4 * t;
        accN  = tail3(d0,     cnt, m0, w0, p0, C0.x, C0.y, C0.z);
        accN += tail3(d0 + 1, cnt, m1, w1, p1, C1.x, C1.y, C1.z);
        accN += tail3(d0 + 2, cnt, m2, w2, p2, C2.x, C2.y, C2.z);
        accN += tail3(d0 + 3, cnt, m3, w3, p3, C3.x, C3.y, C3.z);
    }

    // CRP (fully telescoped): Sum_k lgamma(cnt_k) - lgamma(T+1) per batch row
    if (t == 0) {
        if (cnt > 0) accN += fast_lgamma((float)cnt);
        if (k == 0)  accN -= lgammaf((float)(TN + 1));
    }

    // 2-warp reduction
    const int lane = t & 31, wid = t >> 5;
#pragma unroll
    for (int o = 16; o; o >>= 1)
        accN += __shfl_down_sync(0xffffffffu, accN, o);
    __shared__ float wsum[2];
    if (lane == 0) wsum[wid] = accN;
    __syncthreads();
    if (t == 0)
        atomicAdd(&out[b], -(wsum[0] + wsum[1]));
}

// ---------------------------------------------------------------------------
// Entry point. Inputs: X, loc, log_mean_conc, log_conc, log_scale,
// sparse_prior_logit, z. Output: float[BN].
// ---------------------------------------------------------------------------
extern "C" void kernel_launch(void* const* d_in, const int* in_sizes, int n_in,
                              void* d_out, int out_size)
{
    const float* X   = (const float*)d_in[0];
    const float* loc = (const float*)d_in[1];
    const float* lmc = (const float*)d_in[2];
    const float* lc  = (const float*)d_in[3];
    const float* ls  = (const float*)d_in[4];
    const float* spl = (const float*)d_in[5];
    const int*   z   = (const int*)d_in[6];
    float* out = (float*)d_out;

    k_prep<<<MMAXT + BN / 8, 256>>>(loc, lmc, lc, ls, spl, z, out);
    k_main<<<BN * KMAX, 64>>>(X, out);
}